// round 2
// baseline (speedup 1.0000x reference)
#include <cuda_runtime.h>

#define CH     128
#define NRELS  7
#define NTYPES 4
#define NSLOT  11              // 7 relation slots + 4 root slots
#define KTOT   (NSLOT * CH)    // 1408
#define MAX_TGT 50000

// Scratch (allocation-free rule: __device__ globals)
static __device__ float g_agg[(size_t)MAX_TGT * NSLOT * CH];   // ~281.6 MB
static __device__ int   g_cnt[MAX_TGT * NSLOT];
static __device__ float g_W[KTOT * CH];                        // W_cat[k'][o]

// ---------------------------------------------------------------------------
__global__ void zero_kernel(int n_tgt) {
    size_t stride = (size_t)gridDim.x * blockDim.x;
    size_t i0 = (size_t)blockIdx.x * blockDim.x + threadIdx.x;
    size_t n4 = (size_t)n_tgt * NSLOT * CH / 4;
    float4 z = make_float4(0.f, 0.f, 0.f, 0.f);
    float4* p = reinterpret_cast<float4*>(g_agg);
    for (size_t i = i0; i < n4; i += stride) p[i] = z;
    size_t nc = (size_t)n_tgt * NSLOT;
    for (size_t i = i0; i < nc; i += stride) g_cnt[i] = 0;
}

// Pack W_cat[k'][o]:  k' = slot*128 + k ; slots 0..6 = rel_w, 7..10 = root_w
__global__ void pack_w_kernel(const float* __restrict__ rel_w,
                              const float* __restrict__ root_w) {
    int idx = blockIdx.x * blockDim.x + threadIdx.x;
    if (idx >= KTOT * CH) return;
    int o  = idx & (CH - 1);
    int kp = idx >> 7;          // 0..1407
    int r  = kp >> 7;           // slot
    int k  = kp & (CH - 1);
    float v;
    if (r < NRELS) v = rel_w[((size_t)r * CH + o) * CH + k];
    else           v = root_w[((size_t)(r - NRELS) * CH + o) * CH + k];
    g_W[(size_t)kp * CH + o] = v;
}

// Copy x_target into root slot (7 + node_type); one warp per target row
__global__ void root_copy_kernel(const float4* __restrict__ x_tgt,
                                 const int* __restrict__ t_type, int n_tgt) {
    int warp = (blockIdx.x * blockDim.x + threadIdx.x) >> 5;
    int lane = threadIdx.x & 31;
    if (warp >= n_tgt) return;
    int ty = t_type[warp];
    float4 v = x_tgt[(size_t)warp * (CH / 4) + lane];
    reinterpret_cast<float4*>(
        g_agg + ((size_t)warp * NSLOT + NRELS + ty) * CH)[lane] = v;
}

// One warp per edge: gather 512B source row, atomic-add into agg[dst][etype]
__global__ void scatter_kernel(const float4* __restrict__ x_src,
                               const int* __restrict__ e_src,
                               const int* __restrict__ e_dst,
                               const int* __restrict__ e_type,
                               int n_edges) {
    int warp = (blockIdx.x * blockDim.x + threadIdx.x) >> 5;
    int lane = threadIdx.x & 31;
    if (warp >= n_edges) return;
    int s = e_src[warp];
    int d = e_dst[warp];
    int r = e_type[warp];
    float4 v = x_src[(size_t)s * (CH / 4) + lane];
    float* dst = g_agg + ((size_t)d * NSLOT + r) * CH + lane * 4;
    atomicAdd(dst + 0, v.x);
    atomicAdd(dst + 1, v.y);
    atomicAdd(dst + 2, v.z);
    atomicAdd(dst + 3, v.w);
    if (lane == 0) atomicAdd(&g_cnt[d * NSLOT + r], 1);
}

// ---------------------------------------------------------------------------
// Fused GEMM: out[t][o] = sum_{k'} scale(t, k'>>7) * agg[t][k'] * W_cat[k'][o]
//             + root_b[t_type[t]][o]
// Tile 128x128, BK=16, 256 threads, 8x8 per-thread micro-tile.
#define BM 128
#define BN 128
#define BK 16

__global__ __launch_bounds__(256) void gemm_kernel(
    const int* __restrict__ t_type,
    const float* __restrict__ root_b,
    float* __restrict__ out, int n_tgt)
{
    __shared__ float As[BK][BM + 4];   // [k][m], padded vs bank conflicts
    __shared__ float Bs[BK][BN + 4];

    int tid = threadIdx.x;
    int tx = tid & 15;    // n direction (0..15)
    int ty = tid >> 4;    // m direction (0..15)
    int m_base = blockIdx.x * BM;

    float acc[8][8];
#pragma unroll
    for (int i = 0; i < 8; i++)
#pragma unroll
        for (int j = 0; j < 8; j++) acc[i][j] = 0.f;

    for (int k0 = 0; k0 < KTOT; k0 += BK) {
        int r = k0 >> 7;   // BK divides 128 -> tile lies in one slot
        // Load A tile (128 rows x 16 k), fused mean-scaling
#pragma unroll
        for (int l = 0; l < 2; l++) {
            int e   = tid + l * 256;     // float4 id 0..511
            int row = e >> 2;            // 0..127
            int c4  = (e & 3) * 4;       // k offset 0,4,8,12
            int t = m_base + row;
            float4 v = make_float4(0.f, 0.f, 0.f, 0.f);
            float scale = 1.f;
            if (t < n_tgt) {
                v = *reinterpret_cast<const float4*>(
                    &g_agg[(size_t)t * KTOT + k0 + c4]);
                if (r < NRELS) {
                    int c = g_cnt[t * NSLOT + r];
                    scale = 1.f / (float)max(c, 1);
                }
            }
            As[c4 + 0][row] = v.x * scale;
            As[c4 + 1][row] = v.y * scale;
            As[c4 + 2][row] = v.z * scale;
            As[c4 + 3][row] = v.w * scale;
        }
        // Load B tile (16 k x 128 o), fully coalesced
#pragma unroll
        for (int l = 0; l < 2; l++) {
            int e    = tid + l * 256;
            int krow = e >> 5;           // 0..15
            int n4   = (e & 31) * 4;
            float4 v = *reinterpret_cast<const float4*>(
                &g_W[(size_t)(k0 + krow) * CH + n4]);
            *reinterpret_cast<float4*>(&Bs[krow][n4]) = v;
        }
        __syncthreads();

#pragma unroll
        for (int kk = 0; kk < BK; kk++) {
            float a[8], b[8];
            float4 a0 = *reinterpret_cast<const float4*>(&As[kk][ty * 4]);
            float4 a1 = *reinterpret_cast<const float4*>(&As[kk][ty * 4 + 64]);
            float4 b0 = *reinterpret_cast<const float4*>(&Bs[kk][tx * 4]);
            float4 b1 = *reinterpret_cast<const float4*>(&Bs[kk][tx * 4 + 64]);
            a[0]=a0.x; a[1]=a0.y; a[2]=a0.z; a[3]=a0.w;
            a[4]=a1.x; a[5]=a1.y; a[6]=a1.z; a[7]=a1.w;
            b[0]=b0.x; b[1]=b0.y; b[2]=b0.z; b[3]=b0.w;
            b[4]=b1.x; b[5]=b1.y; b[6]=b1.z; b[7]=b1.w;
#pragma unroll
            for (int i = 0; i < 8; i++)
#pragma unroll
                for (int j = 0; j < 8; j++) acc[i][j] += a[i] * b[j];
        }
        __syncthreads();
    }

    // Epilogue: add per-type bias, store
#pragma unroll
    for (int i = 0; i < 8; i++) {
        int m = (i < 4) ? (ty * 4 + i) : (64 + ty * 4 + (i - 4));
        int t = m_base + m;
        if (t >= n_tgt) continue;
        int nty = t_type[t];
        const float* bias = root_b + (size_t)nty * CH;
        float* orow = out + (size_t)t * CH;
        float4 bb0 = *reinterpret_cast<const float4*>(&bias[tx * 4]);
        float4 bb1 = *reinterpret_cast<const float4*>(&bias[tx * 4 + 64]);
        float4 o0 = make_float4(acc[i][0] + bb0.x, acc[i][1] + bb0.y,
                                acc[i][2] + bb0.z, acc[i][3] + bb0.w);
        float4 o1 = make_float4(acc[i][4] + bb1.x, acc[i][5] + bb1.y,
                                acc[i][6] + bb1.z, acc[i][7] + bb1.w);
        *reinterpret_cast<float4*>(&orow[tx * 4])      = o0;
        *reinterpret_cast<float4*>(&orow[tx * 4 + 64]) = o1;
    }
}

// ---------------------------------------------------------------------------
extern "C" void kernel_launch(void* const* d_in, const int* in_sizes, int n_in,
                              void* d_out, int out_size) {
    const float* x_src  = (const float*)d_in[0];
    const float* x_tgt  = (const float*)d_in[1];
    const float* rel_w  = (const float*)d_in[2];
    const float* root_w = (const float*)d_in[3];
    const float* root_b = (const float*)d_in[4];
    const int* e_src    = (const int*)d_in[5];
    const int* e_dst    = (const int*)d_in[6];
    const int* e_type   = (const int*)d_in[7];
    const int* t_type   = (const int*)d_in[8];
    float* out = (float*)d_out;

    int n_tgt   = in_sizes[1] / CH;
    int n_edges = in_sizes[5];

    zero_kernel<<<2048, 256>>>(n_tgt);
    pack_w_kernel<<<(KTOT * CH + 255) / 256, 256>>>(rel_w, root_w);
    root_copy_kernel<<<(n_tgt * 32 + 255) / 256, 256>>>(
        (const float4*)x_tgt, t_type, n_tgt);
    scatter_kernel<<<(n_edges * 32 + 255) / 256, 256>>>(
        (const float4*)x_src, e_src, e_dst, e_type, n_edges);
    gemm_kernel<<<(n_tgt + BM - 1) / BM, 256>>>(t_type, root_b, out, n_tgt);
}

// round 5
// speedup vs baseline: 1.6257x; 1.6257x over previous
#include <cuda_runtime.h>
#include <cuda_bf16.h>
#include <cstdint>

#define CH      128
#define NRELS   7
#define NSLOT   11
#define KTOT    (NSLOT * CH)      // 1408 fp32 K
#define MAX_TGT 50000
#define NITER   22                // 64 fp32-k per outer iteration

static __device__ float          g_agg[(size_t)MAX_TGT * KTOT];   // ~281.6 MB
static __device__ int            g_cnt[MAX_TGT * NSLOT];
static __device__ __nv_bfloat16  g_Wh[(size_t)CH * KTOT];         // hi bf16, [n][k]
static __device__ __nv_bfloat16  g_Wl[(size_t)CH * KTOT];         // lo bf16, [n][k]

// ===================== helpers ============================================
__device__ __forceinline__ uint32_t smem_u32(const void* p) {
    uint32_t a;
    asm("{ .reg .u64 t; cvta.to.shared.u64 t, %1; cvt.u32.u64 %0, t; }"
        : "=r"(a) : "l"(p));
    return a;
}
__device__ __forceinline__ uint32_t sw128(uint32_t b) { return b ^ ((b >> 3) & 0x70); }

__device__ __forceinline__ void split2(float x, float y, uint32_t& hi, uint32_t& lo) {
    __nv_bfloat16 hx = __float2bfloat16(x), hy = __float2bfloat16(y);
    __nv_bfloat16 lx = __float2bfloat16(x - __bfloat162float(hx));
    __nv_bfloat16 ly = __float2bfloat16(y - __bfloat162float(hy));
    hi = ((uint32_t)__bfloat16_as_ushort(hy) << 16) | (uint32_t)__bfloat16_as_ushort(hx);
    lo = ((uint32_t)__bfloat16_as_ushort(ly) << 16) | (uint32_t)__bfloat16_as_ushort(lx);
}

__device__ __forceinline__ void ldsm_x4(uint32_t& r0, uint32_t& r1,
                                        uint32_t& r2, uint32_t& r3, uint32_t addr) {
    asm volatile("ldmatrix.sync.aligned.m8n8.x4.shared.b16 {%0,%1,%2,%3}, [%4];"
                 : "=r"(r0), "=r"(r1), "=r"(r2), "=r"(r3) : "r"(addr));
}
__device__ __forceinline__ void mma16816(float* c, const uint32_t* a, const uint32_t* b) {
    asm volatile("mma.sync.aligned.m16n8k16.row.col.f32.bf16.bf16.f32 "
                 "{%0,%1,%2,%3}, {%4,%5,%6,%7}, {%8,%9}, {%0,%1,%2,%3};"
                 : "+f"(c[0]), "+f"(c[1]), "+f"(c[2]), "+f"(c[3])
                 : "r"(a[0]), "r"(a[1]), "r"(a[2]), "r"(a[3]), "r"(b[0]), "r"(b[1]));
}

// ===================== prep kernels =======================================
__global__ void zero_kernel(int n_tgt) {
    size_t stride = (size_t)gridDim.x * blockDim.x;
    size_t i0 = (size_t)blockIdx.x * blockDim.x + threadIdx.x;
    size_t n4 = (size_t)n_tgt * (NRELS * CH / 4);
    float4 z = make_float4(0.f, 0.f, 0.f, 0.f);
    for (size_t i = i0; i < n4; i += stride) {
        size_t t = i / (NRELS * CH / 4);
        size_t o = i % (NRELS * CH / 4);
        reinterpret_cast<float4*>(g_agg + t * KTOT)[o] = z;
    }
    size_t nc = (size_t)n_tgt * NSLOT;
    for (size_t i = i0; i < nc; i += stride) g_cnt[i] = 0;
}

// g_Wh/g_Wl[n][k] = hi/lo bf16 of W_cat[k][n]
__global__ void pack_wb_kernel(const float* __restrict__ rel_w,
                               const float* __restrict__ root_w) {
    int idx = blockIdx.x * blockDim.x + threadIdx.x;
    if (idx >= CH * KTOT) return;
    int n = idx / KTOT, k = idx % KTOT;
    int slot = k >> 7, kk = k & 127;
    float w = (slot < NRELS)
                  ? rel_w[((size_t)slot * CH + n) * CH + kk]
                  : root_w[((size_t)(slot - NRELS) * CH + n) * CH + kk];
    __nv_bfloat16 h = __float2bfloat16(w);
    __nv_bfloat16 l = __float2bfloat16(w - __bfloat162float(h));
    g_Wh[(size_t)n * KTOT + k] = h;
    g_Wl[(size_t)n * KTOT + k] = l;
}

__global__ void root_copy_kernel(const float4* __restrict__ x_tgt,
                                 const int* __restrict__ t_type, int n_tgt) {
    int warp = (blockIdx.x * blockDim.x + threadIdx.x) >> 5;
    int lane = threadIdx.x & 31;
    if (warp >= n_tgt) return;
    int ty = t_type[warp];
    float4 v = x_tgt[(size_t)warp * (CH / 4) + lane];
    float4 z = make_float4(0.f, 0.f, 0.f, 0.f);
    float4* base = reinterpret_cast<float4*>(g_agg + (size_t)warp * KTOT + NRELS * CH);
#pragma unroll
    for (int s = 0; s < 4; s++) base[s * (CH / 4) + lane] = (s == ty) ? v : z;
}

__global__ void scatter_kernel(const float4* __restrict__ x_src,
                               const int* __restrict__ e_src,
                               const int* __restrict__ e_dst,
                               const int* __restrict__ e_type,
                               int n_edges) {
    int warp = (blockIdx.x * blockDim.x + threadIdx.x) >> 5;
    int lane = threadIdx.x & 31;
    if (warp >= n_edges) return;
    int s = e_src[warp];
    int d = e_dst[warp];
    int r = e_type[warp];
    float4 v = x_src[(size_t)s * (CH / 4) + lane];
    float* dst = g_agg + (size_t)d * KTOT + r * CH + lane * 4;
    atomicAdd(dst + 0, v.x);
    atomicAdd(dst + 1, v.y);
    atomicAdd(dst + 2, v.z);
    atomicAdd(dst + 3, v.w);
    if (lane == 0) atomicAdd(&g_cnt[d * NSLOT + r], 1);
}

// ===================== mma.sync split-bf16 GEMM ===========================
// out = A(128 x 1408 fp32) . W^T with 3-product split-bf16:
//   a.w ~= ah.wh + al.wh + ah.wl   (error ~2^-17)
// Per iter: 64 fp32-k -> tiles Ah, Al, Wh, Wl (128 rows x 64 bf16, SW128).
#define SMEM_BYTES 65536

__global__ __launch_bounds__(256) void gemm_mma_kernel(
    const int* __restrict__ t_type,
    const float* __restrict__ root_b,
    float* __restrict__ out, int n_tgt)
{
    extern __shared__ __align__(1024) char smem[];
    char* sAh = smem;
    char* sAl = smem + 16384;
    char* sBh = smem + 32768;
    char* sBl = smem + 49152;

    int tid = threadIdx.x, lane = tid & 31, wid = tid >> 5;
    int wm = wid & 3, wn = wid >> 2;          // 4x2 warp grid (warp tile 32x64)
    int m_base = blockIdx.x * 128;

    // staging role: one half-row per thread (32 fp32 of A, 32 bf16 of each W)
    int row = tid >> 1, half = tid & 1;
    int t = m_base + row;
    bool valid = t < n_tgt;

    float acc[2][8][4];
#pragma unroll
    for (int i = 0; i < 2; i++)
#pragma unroll
        for (int g = 0; g < 8; g++)
#pragma unroll
            for (int j = 0; j < 4; j++) acc[i][g][j] = 0.f;

    float4 pa[8];
    uint4  pbh[4], pbl[4];
    int    pc;
    const float4 z4 = make_float4(0.f, 0.f, 0.f, 0.f);

    const float* aRow  = g_agg + (valid ? (size_t)t * KTOT : 0) + half * 32;
    const char*  whRow = reinterpret_cast<const char*>(g_Wh)
                       + (size_t)row * (KTOT * 2) + half * 64;
    const char*  wlRow = reinterpret_cast<const char*>(g_Wl)
                       + (size_t)row * (KTOT * 2) + half * 64;

    // prefetch iter 0
    {
        const float4* asrc = reinterpret_cast<const float4*>(aRow);
#pragma unroll
        for (int i = 0; i < 8; i++) pa[i] = valid ? asrc[i] : z4;
#pragma unroll
        for (int i = 0; i < 4; i++) {
            pbh[i] = reinterpret_cast<const uint4*>(whRow)[i];
            pbl[i] = reinterpret_cast<const uint4*>(wlRow)[i];
        }
        pc = valid ? g_cnt[t * NSLOT + 0] : -1;
    }

    uint32_t ahB = smem_u32(sAh), alB = smem_u32(sAl);
    uint32_t bhB = smem_u32(sBh), blB = smem_u32(sBl);
    uint32_t stsOff = sw128((uint32_t)(row * 128 + half * 64));
    // ldmatrix per-lane coordinates (verified layout)
    int a_m  = wm * 32 + ((lane >> 3) & 1) * 8 + (lane & 7);
    int a_kb = (lane >> 4) * 16;
    int b_n  = wn * 64 + (lane >> 4) * 8 + (lane & 7);
    int b_kb = ((lane >> 3) & 1) * 16;

    for (int it = 0; it < NITER; ++it) {
        if (it > 0) __syncthreads();          // previous compute done
        // ---- STS staged tiles ----
        float scale = (pc < 1) ? 1.f : (1.f / (float)pc);
#pragma unroll
        for (int i = 0; i < 4; i++) {
            float4 v0 = pa[2 * i], v1 = pa[2 * i + 1];
            uint4 uh, ul;
            split2(v0.x * scale, v0.y * scale, uh.x, ul.x);
            split2(v0.z * scale, v0.w * scale, uh.y, ul.y);
            split2(v1.x * scale, v1.y * scale, uh.z, ul.z);
            split2(v1.z * scale, v1.w * scale, uh.w, ul.w);
            uint32_t off = stsOff ^ (i * 16);
            *reinterpret_cast<uint4*>(sAh + off) = uh;
            *reinterpret_cast<uint4*>(sAl + off) = ul;
            *reinterpret_cast<uint4*>(sBh + off) = pbh[i];
            *reinterpret_cast<uint4*>(sBl + off) = pbl[i];
        }
        // ---- prefetch next iter (overlaps compute below) ----
        if (it + 1 < NITER) {
            int nit = it + 1;
            const float4* asrc =
                reinterpret_cast<const float4*>(aRow + (size_t)nit * 64);
#pragma unroll
            for (int i = 0; i < 8; i++) pa[i] = valid ? asrc[i] : z4;
#pragma unroll
            for (int i = 0; i < 4; i++) {
                pbh[i] = *reinterpret_cast<const uint4*>(whRow + (size_t)nit * 128 + i * 16);
                pbl[i] = *reinterpret_cast<const uint4*>(wlRow + (size_t)nit * 128 + i * 16);
            }
            int r = nit >> 1;
            pc = (valid && r < NRELS) ? g_cnt[t * NSLOT + r] : -1;
        }
        __syncthreads();

        // ---- compute: 4 k16 steps, 3 products each ----
#pragma unroll
        for (int ks = 0; ks < 4; ks++) {
            uint32_t ah[2][4], al[2][4];
#pragma unroll
            for (int tm = 0; tm < 2; tm++) {
                uint32_t off = sw128((uint32_t)((a_m + tm * 16) * 128 + ks * 32 + a_kb));
                ldsm_x4(ah[tm][0], ah[tm][1], ah[tm][2], ah[tm][3], ahB + off);
                ldsm_x4(al[tm][0], al[tm][1], al[tm][2], al[tm][3], alB + off);
            }
            uint32_t bh[8][2], bl[8][2];
#pragma unroll
            for (int g2 = 0; g2 < 8; g2 += 2) {
                uint32_t off = sw128((uint32_t)((b_n + g2 * 8) * 128 + ks * 32 + b_kb));
                ldsm_x4(bh[g2][0], bh[g2][1], bh[g2 + 1][0], bh[g2 + 1][1], bhB + off);
                ldsm_x4(bl[g2][0], bl[g2][1], bl[g2 + 1][0], bl[g2 + 1][1], blB + off);
            }
#pragma unroll
            for (int tm = 0; tm < 2; tm++)
#pragma unroll
                for (int g = 0; g < 8; g++) {
                    mma16816(acc[tm][g], ah[tm], bh[g]);
                    mma16816(acc[tm][g], al[tm], bh[g]);
                    mma16816(acc[tm][g], ah[tm], bl[g]);
                }
        }
    }

    // ---- epilogue: bias + store ----
#pragma unroll
    for (int tm = 0; tm < 2; tm++) {
        int r0 = m_base + wm * 32 + tm * 16 + (lane >> 2);
#pragma unroll
        for (int w = 0; w < 2; w++) {
            int rr = r0 + w * 8;
            if (rr >= n_tgt) continue;
            int ty = t_type[rr];
            const float* bias = root_b + (size_t)ty * CH;
            float* orow = out + (size_t)rr * CH;
            int col0 = wn * 64 + (lane & 3) * 2;
#pragma unroll
            for (int g = 0; g < 8; g++) {
                int c = col0 + g * 8;
                float2 o;
                o.x = acc[tm][g][w * 2 + 0] + bias[c];
                o.y = acc[tm][g][w * 2 + 1] + bias[c + 1];
                *reinterpret_cast<float2*>(&orow[c]) = o;
            }
        }
    }
}

// ===================== launch =============================================
extern "C" void kernel_launch(void* const* d_in, const int* in_sizes, int n_in,
                              void* d_out, int out_size) {
    const float* x_src  = (const float*)d_in[0];
    const float* x_tgt  = (const float*)d_in[1];
    const float* rel_w  = (const float*)d_in[2];
    const float* root_w = (const float*)d_in[3];
    const float* root_b = (const float*)d_in[4];
    const int* e_src    = (const int*)d_in[5];
    const int* e_dst    = (const int*)d_in[6];
    const int* e_type   = (const int*)d_in[7];
    const int* t_type   = (const int*)d_in[8];
    float* out = (float*)d_out;

    int n_tgt   = in_sizes[1] / CH;
    int n_edges = in_sizes[5];

    cudaFuncSetAttribute(gemm_mma_kernel,
                         cudaFuncAttributeMaxDynamicSharedMemorySize, SMEM_BYTES);

    zero_kernel<<<2048, 256>>>(n_tgt);
    pack_wb_kernel<<<(CH * KTOT + 255) / 256, 256>>>(rel_w, root_w);
    root_copy_kernel<<<(n_tgt * 32 + 255) / 256, 256>>>(
        (const float4*)x_tgt, t_type, n_tgt);
    scatter_kernel<<<(n_edges * 32 + 255) / 256, 256>>>(
        (const float4*)x_src, e_src, e_dst, e_type, n_edges);
    gemm_mma_kernel<<<(n_tgt + 127) / 128, 256, SMEM_BYTES>>>(
        t_type, root_b, out, n_tgt);
}

// round 6
// speedup vs baseline: 2.1825x; 1.3425x over previous
#include <cuda_runtime.h>
#include <cuda_bf16.h>
#include <cstdint>

#define CH      128
#define NRELS   7
#define KAGG    (NRELS * CH)      // 896 fp32 K held in g_agg
#define KTOT    1408              // 896 rel + 512 virtual root K
#define MAX_TGT 50000
#define NITER   22                // 64 fp32-k per outer iteration (14 rel + 8 root)

static __device__ float          g_agg[(size_t)MAX_TGT * KAGG];   // ~179 MB
static __device__ int            g_cnt[MAX_TGT * NRELS];
static __device__ __nv_bfloat16  g_Wh[(size_t)CH * KTOT];         // hi bf16, [n][k]
static __device__ __nv_bfloat16  g_Wl[(size_t)CH * KTOT];         // lo bf16, [n][k]

// ===================== helpers ============================================
__device__ __forceinline__ uint32_t smem_u32(const void* p) {
    uint32_t a;
    asm("{ .reg .u64 t; cvta.to.shared.u64 t, %1; cvt.u32.u64 %0, t; }"
        : "=r"(a) : "l"(p));
    return a;
}
__device__ __forceinline__ uint32_t sw128(uint32_t b) { return b ^ ((b >> 3) & 0x70); }

__device__ __forceinline__ void split2(float x, float y, uint32_t& hi, uint32_t& lo) {
    __nv_bfloat16 hx = __float2bfloat16(x), hy = __float2bfloat16(y);
    __nv_bfloat16 lx = __float2bfloat16(x - __bfloat162float(hx));
    __nv_bfloat16 ly = __float2bfloat16(y - __bfloat162float(hy));
    hi = ((uint32_t)__bfloat16_as_ushort(hy) << 16) | (uint32_t)__bfloat16_as_ushort(hx);
    lo = ((uint32_t)__bfloat16_as_ushort(ly) << 16) | (uint32_t)__bfloat16_as_ushort(lx);
}

__device__ __forceinline__ void ldsm_x4(uint32_t& r0, uint32_t& r1,
                                        uint32_t& r2, uint32_t& r3, uint32_t addr) {
    asm volatile("ldmatrix.sync.aligned.m8n8.x4.shared.b16 {%0,%1,%2,%3}, [%4];"
                 : "=r"(r0), "=r"(r1), "=r"(r2), "=r"(r3) : "r"(addr));
}
__device__ __forceinline__ void mma16816(float* c, const uint32_t* a, const uint32_t* b) {
    asm volatile("mma.sync.aligned.m16n8k16.row.col.f32.bf16.bf16.f32 "
                 "{%0,%1,%2,%3}, {%4,%5,%6,%7}, {%8,%9}, {%0,%1,%2,%3};"
                 : "+f"(c[0]), "+f"(c[1]), "+f"(c[2]), "+f"(c[3])
                 : "r"(a[0]), "r"(a[1]), "r"(a[2]), "r"(a[3]), "r"(b[0]), "r"(b[1]));
}

// ===================== prep kernels =======================================
__global__ void zero_kernel(int n_tgt) {
    size_t stride = (size_t)gridDim.x * blockDim.x;
    size_t i0 = (size_t)blockIdx.x * blockDim.x + threadIdx.x;
    size_t n4 = (size_t)n_tgt * (KAGG / 4);
    float4 z = make_float4(0.f, 0.f, 0.f, 0.f);
    float4* p = reinterpret_cast<float4*>(g_agg);
    for (size_t i = i0; i < n4; i += stride) p[i] = z;
    size_t nc = (size_t)n_tgt * NRELS;
    for (size_t i = i0; i < nc; i += stride) g_cnt[i] = 0;
}

// g_Wh/g_Wl[n][k] = hi/lo bf16 of W_cat[k][n]  (k: 0..895 rel, 896..1407 root)
__global__ void pack_wb_kernel(const float* __restrict__ rel_w,
                               const float* __restrict__ root_w) {
    int idx = blockIdx.x * blockDim.x + threadIdx.x;
    if (idx >= CH * KTOT) return;
    int n = idx / KTOT, k = idx % KTOT;
    int slot = k >> 7, kk = k & 127;
    float w = (slot < NRELS)
                  ? rel_w[((size_t)slot * CH + n) * CH + kk]
                  : root_w[((size_t)(slot - NRELS) * CH + n) * CH + kk];
    __nv_bfloat16 h = __float2bfloat16(w);
    __nv_bfloat16 l = __float2bfloat16(w - __bfloat162float(h));
    g_Wh[(size_t)n * KTOT + k] = h;
    g_Wl[(size_t)n * KTOT + k] = l;
}

// One warp per edge: gather 512B row, one v4 reduction per lane
__global__ void scatter_kernel(const float4* __restrict__ x_src,
                               const int* __restrict__ e_src,
                               const int* __restrict__ e_dst,
                               const int* __restrict__ e_type,
                               int n_edges) {
    int warp = (blockIdx.x * blockDim.x + threadIdx.x) >> 5;
    int lane = threadIdx.x & 31;
    if (warp >= n_edges) return;
    int s = e_src[warp];
    int d = e_dst[warp];
    int r = e_type[warp];
    float4 v = x_src[(size_t)s * (CH / 4) + lane];
    float* dst = g_agg + (size_t)d * KAGG + r * CH + lane * 4;
    asm volatile("red.global.add.v4.f32 [%0], {%1,%2,%3,%4};"
                 :: "l"(dst), "f"(v.x), "f"(v.y), "f"(v.z), "f"(v.w) : "memory");
    if (lane == 0) atomicAdd(&g_cnt[d * NRELS + r], 1);
}

// ===================== mma.sync split-bf16 GEMM ===========================
// out = [A_rel | A_root](128 x 1408 fp32) . W^T, 3-product split-bf16:
//   a.w ~= ah.wh + al.wh + ah.wl  (error ~2^-17)
// Iters 0..13: A from g_agg (fused 1/cnt). Iters 14..21: virtual root slots,
// A row = x_tgt[t] iff slot==node_type(t), else zeros (no memory traffic).
#define SMEM_BYTES 65536

__global__ __launch_bounds__(256) void gemm_mma_kernel(
    const float* __restrict__ x_tgt,
    const int* __restrict__ t_type,
    const float* __restrict__ root_b,
    float* __restrict__ out, int n_tgt)
{
    extern __shared__ __align__(1024) char smem[];
    char* sAh = smem;
    char* sAl = smem + 16384;
    char* sBh = smem + 32768;
    char* sBl = smem + 49152;

    int tid = threadIdx.x, lane = tid & 31, wid = tid >> 5;
    int wm = wid & 3, wn = wid >> 2;          // 4x2 warp grid (warp tile 32x64)
    int m_base = blockIdx.x * 128;

    int row = tid >> 1, half = tid & 1;       // staging: one half-row per thread
    int t = m_base + row;
    bool valid = t < n_tgt;
    int ty = valid ? t_type[t] : -1;

    float acc[2][8][4];
#pragma unroll
    for (int i = 0; i < 2; i++)
#pragma unroll
        for (int g = 0; g < 8; g++)
#pragma unroll
            for (int j = 0; j < 4; j++) acc[i][g][j] = 0.f;

    float4 pa[8];
    uint4  pbh[4], pbl[4];
    int    pc;
    const float4 z4 = make_float4(0.f, 0.f, 0.f, 0.f);

    const float* aRow  = g_agg + (valid ? (size_t)t * KAGG : 0) + half * 32;
    const float* xtRow = x_tgt + (valid ? (size_t)t * CH : 0) + half * 32;
    const char*  whRow = reinterpret_cast<const char*>(g_Wh)
                       + (size_t)row * (KTOT * 2) + half * 64;
    const char*  wlRow = reinterpret_cast<const char*>(g_Wl)
                       + (size_t)row * (KTOT * 2) + half * 64;

    // ---- A prefetch for iteration `nit` ----
    auto prefA = [&](int nit) {
        if (nit < 14) {                        // relation slots from g_agg
            const float4* asrc =
                reinterpret_cast<const float4*>(aRow + (size_t)nit * 64);
#pragma unroll
            for (int i = 0; i < 8; i++) pa[i] = valid ? asrc[i] : z4;
            pc = valid ? g_cnt[t * NRELS + (nit >> 1)] : -1;
        } else {                               // virtual root slots from x_tgt
            int s = (nit - 14) >> 1;
            bool live = valid && (ty == s);
            const float4* asrc = reinterpret_cast<const float4*>(
                xtRow + ((nit - 14) & 1) * 64);
#pragma unroll
            for (int i = 0; i < 8; i++) pa[i] = live ? asrc[i] : z4;
            pc = -1;
        }
    };

    // prefetch iter 0
    prefA(0);
#pragma unroll
    for (int i = 0; i < 4; i++) {
        pbh[i] = reinterpret_cast<const uint4*>(whRow)[i];
        pbl[i] = reinterpret_cast<const uint4*>(wlRow)[i];
    }

    uint32_t ahB = smem_u32(sAh), alB = smem_u32(sAl);
    uint32_t bhB = smem_u32(sBh), blB = smem_u32(sBl);
    uint32_t stsOff = sw128((uint32_t)(row * 128 + half * 64));
    int a_m  = wm * 32 + ((lane >> 3) & 1) * 8 + (lane & 7);
    int a_kb = (lane >> 4) * 16;
    int b_n  = wn * 64 + (lane >> 4) * 8 + (lane & 7);
    int b_kb = ((lane >> 3) & 1) * 16;

    for (int it = 0; it < NITER; ++it) {
        if (it > 0) __syncthreads();
        // ---- STS staged tiles ----
        float scale = (pc < 1) ? 1.f : (1.f / (float)pc);
#pragma unroll
        for (int i = 0; i < 4; i++) {
            float4 v0 = pa[2 * i], v1 = pa[2 * i + 1];
            uint4 uh, ul;
            split2(v0.x * scale, v0.y * scale, uh.x, ul.x);
            split2(v0.z * scale, v0.w * scale, uh.y, ul.y);
            split2(v1.x * scale, v1.y * scale, uh.z, ul.z);
            split2(v1.z * scale, v1.w * scale, uh.w, ul.w);
            uint32_t off = stsOff ^ (i * 16);
            *reinterpret_cast<uint4*>(sAh + off) = uh;
            *reinterpret_cast<uint4*>(sAl + off) = ul;
            *reinterpret_cast<uint4*>(sBh + off) = pbh[i];
            *reinterpret_cast<uint4*>(sBl + off) = pbl[i];
        }
        // ---- prefetch next iter (overlaps compute) ----
        if (it + 1 < NITER) {
            int nit = it + 1;
            prefA(nit);
#pragma unroll
            for (int i = 0; i < 4; i++) {
                pbh[i] = *reinterpret_cast<const uint4*>(whRow + (size_t)nit * 128 + i * 16);
                pbl[i] = *reinterpret_cast<const uint4*>(wlRow + (size_t)nit * 128 + i * 16);
            }
        }
        __syncthreads();

        // ---- compute: 4 k16 steps, 3 products each ----
#pragma unroll
        for (int ks = 0; ks < 4; ks++) {
            uint32_t ah[2][4], al[2][4];
#pragma unroll
            for (int tm = 0; tm < 2; tm++) {
                uint32_t off = sw128((uint32_t)((a_m + tm * 16) * 128 + ks * 32 + a_kb));
                ldsm_x4(ah[tm][0], ah[tm][1], ah[tm][2], ah[tm][3], ahB + off);
                ldsm_x4(al[tm][0], al[tm][1], al[tm][2], al[tm][3], alB + off);
            }
            uint32_t bh[8][2], bl[8][2];
#pragma unroll
            for (int g2 = 0; g2 < 8; g2 += 2) {
                uint32_t off = sw128((uint32_t)((b_n + g2 * 8) * 128 + ks * 32 + b_kb));
                ldsm_x4(bh[g2][0], bh[g2][1], bh[g2 + 1][0], bh[g2 + 1][1], bhB + off);
                ldsm_x4(bl[g2][0], bl[g2][1], bl[g2 + 1][0], bl[g2 + 1][1], blB + off);
            }
#pragma unroll
            for (int tm = 0; tm < 2; tm++)
#pragma unroll
                for (int g = 0; g < 8; g++) {
                    mma16816(acc[tm][g], ah[tm], bh[g]);
                    mma16816(acc[tm][g], al[tm], bh[g]);
                    mma16816(acc[tm][g], ah[tm], bl[g]);
                }
        }
    }

    // ---- epilogue: bias + store ----
#pragma unroll
    for (int tm = 0; tm < 2; tm++) {
        int r0 = m_base + wm * 32 + tm * 16 + (lane >> 2);
#pragma unroll
        for (int w = 0; w < 2; w++) {
            int rr = r0 + w * 8;
            if (rr >= n_tgt) continue;
            int tyo = t_type[rr];
            const float* bias = root_b + (size_t)tyo * CH;
            float* orow = out + (size_t)rr * CH;
            int col0 = wn * 64 + (lane & 3) * 2;
#pragma unroll
            for (int g = 0; g < 8; g++) {
                int c = col0 + g * 8;
                float2 o;
                o.x = acc[tm][g][w * 2 + 0] + bias[c];
                o.y = acc[tm][g][w * 2 + 1] + bias[c + 1];
                *reinterpret_cast<float2*>(&orow[c]) = o;
            }
        }
    }
}

// ===================== launch =============================================
extern "C" void kernel_launch(void* const* d_in, const int* in_sizes, int n_in,
                              void* d_out, int out_size) {
    const float* x_src  = (const float*)d_in[0];
    const float* x_tgt  = (const float*)d_in[1];
    const float* rel_w  = (const float*)d_in[2];
    const float* root_w = (const float*)d_in[3];
    const float* root_b = (const float*)d_in[4];
    const int* e_src    = (const int*)d_in[5];
    const int* e_dst    = (const int*)d_in[6];
    const int* e_type   = (const int*)d_in[7];
    const int* t_type   = (const int*)d_in[8];
    float* out = (float*)d_out;

    int n_tgt   = in_sizes[1] / CH;
    int n_edges = in_sizes[5];

    cudaFuncSetAttribute(gemm_mma_kernel,
                         cudaFuncAttributeMaxDynamicSharedMemorySize, SMEM_BYTES);

    zero_kernel<<<2048, 256>>>(n_tgt);
    pack_wb_kernel<<<(CH * KTOT + 255) / 256, 256>>>(rel_w, root_w);
    scatter_kernel<<<(n_edges * 32 + 255) / 256, 256>>>(
        (const float4*)x_src, e_src, e_dst, e_type, n_edges);
    gemm_mma_kernel<<<(n_tgt + 127) / 128, 256, SMEM_BYTES>>>(
        x_tgt, t_type, root_b, out, n_tgt);
}